// round 5
// baseline (speedup 1.0000x reference)
#include <cuda_runtime.h>
#include <math.h>

#define NJ 17
#define ND 128
#define NH 2
#define NDH 64
#define NITER 4
#define LNEPS 1e-5f
#define NTHREADS 256
#define XSTR 20          // padded row stride for transposed xn tile (80B: 16B-aligned rows)
#define GRID_PERSIST 296 // 148 SMs x 2 CTAs

typedef unsigned long long ull;

// ---- fixed 17-node skeleton adjacency (incl. self), flattened neighbor lists ----
__constant__ int c_nbr_off[18] = {0,4,7,10,12,15,18,20,23,28,31,33,36,39,41,44,47,49};
__constant__ int c_nbr[49] = {
    0,1,4,7,  0,1,2,  1,2,3,  2,3,  0,4,5,  4,5,6,  5,6,  0,7,8,
    7,8,9,11,14,  8,9,10,  9,10,  8,11,12,  11,12,13,  12,13,
    8,14,15,  14,15,16,  15,16};

// float4/LDS.128 members must be 16B aligned (R1 lesson).
struct SmemLayout {
    alignas(16) float xs[NJ][ND];
    alignas(16) float x0s[NJ][ND];
    alignas(16) float xnT[ND][XSTR];   // row stride 80B (16-mult)
    alignas(16) float Ls[NJ][2*ND];
    alignas(16) float Rs[NJ][2*ND];
    alignas(16) float Vs[NJ][ND];
    alignas(16) float skipv[NJ];
    alignas(16) float lnG[ND];
    alignas(16) float lnB[ND];
    alignas(16) float aW[ND];
    alignas(16) float psW[ND];
    alignas(16) float vbs[ND];
    alignas(16) float b1s[2*ND];
    alignas(16) float b2s[2*ND];
    alignas(16) float ogG[ND];
    alignas(16) float ogB[ND];
    alignas(16) float alpha_b0;
    float ps_b0;
};

__device__ __forceinline__ float wredsum(float v) {
    #pragma unroll
    for (int o = 16; o; o >>= 1) v += __shfl_xor_sync(0xffffffffu, v, o);
    return v;
}

// ---- packed fp32x2 helpers (sm_103a FFMA2 path) ----
__device__ __forceinline__ void ffma2(ull& d, ull a, ull b) {
    asm("fma.rn.f32x2 %0, %1, %2, %0;" : "+l"(d) : "l"(a), "l"(b));
}
__device__ __forceinline__ ull pack2(float lo, float hi) {
    ull r; asm("mov.b64 %0, {%1, %2};" : "=l"(r) : "f"(lo), "f"(hi)); return r;
}
__device__ __forceinline__ float2 unpack2(ull v) {
    float lo, hi; asm("mov.b64 {%0, %1}, %2;" : "=f"(lo), "=f"(hi) : "l"(v));
    return make_float2(lo, hi);
}

__global__ void __launch_bounds__(NTHREADS, 2)
spatial_appnp_kernel(
    const float* __restrict__ x,
    const float* __restrict__ og,  const float* __restrict__ ob,
    const float* __restrict__ lg,  const float* __restrict__ lb,
    const float* __restrict__ aw,  const float* __restrict__ ab,
    const float* __restrict__ w1,  const float* __restrict__ b1,
    const float* __restrict__ w2,  const float* __restrict__ b2,
    const float* __restrict__ psw, const float* __restrict__ psb,
    const float* __restrict__ vw,  const float* __restrict__ vb,
    float* __restrict__ out, int ntiles)
{
    extern __shared__ float smem_raw[];
    SmemLayout* sm = reinterpret_cast<SmemLayout*>(smem_raw);

    const int tid  = threadIdx.x;
    const int lane = tid & 31;
    const int wid  = tid >> 5;

    // ---- one-time parameter staging ----
    for (int i = tid; i < ND; i += NTHREADS) {
        sm->lnG[i] = lg[i]; sm->lnB[i] = lb[i];
        sm->aW[i]  = aw[i]; sm->psW[i] = psw[i];
        sm->vbs[i] = vb[i];
        sm->ogG[i] = og[i]; sm->ogB[i] = ob[i];
    }
    for (int i = tid; i < 2*ND; i += NTHREADS) { sm->b1s[i] = b1[i]; sm->b2s[i] = b2[i]; }
    if (tid == 0) { sm->alpha_b0 = ab[0]; sm->ps_b0 = psb[0]; }

    for (int tile = blockIdx.x; tile < ntiles; tile += gridDim.x) {
        __syncthreads();   // protect xs/x0s reuse across tiles (and initial param stage)

        const float* xg = x + (size_t)tile * NJ * ND;

        // ---- outer LayerNorm: x -> xs, x0s (interleaved channels, one-pass var) ----
        for (int j = wid; j < NJ; j += 8) {
            const float v0 = xg[j*ND + lane];
            const float v1 = xg[j*ND + lane + 32];
            const float v2 = xg[j*ND + lane + 64];
            const float v3 = xg[j*ND + lane + 96];
            float s1 = v0+v1+v2+v3;
            float s2 = v0*v0+v1*v1+v2*v2+v3*v3;
            #pragma unroll
            for (int o = 16; o; o >>= 1) {
                s1 += __shfl_xor_sync(0xffffffffu, s1, o);
                s2 += __shfl_xor_sync(0xffffffffu, s2, o);
            }
            const float mean = s1 * (1.0f/ND);
            const float var  = s2 * (1.0f/ND) - mean*mean;
            const float rs = rsqrtf(var + LNEPS);
            const float y0 = (v0-mean)*rs*sm->ogG[lane     ] + sm->ogB[lane     ];
            const float y1 = (v1-mean)*rs*sm->ogG[lane + 32] + sm->ogB[lane + 32];
            const float y2 = (v2-mean)*rs*sm->ogG[lane + 64] + sm->ogB[lane + 64];
            const float y3 = (v3-mean)*rs*sm->ogG[lane + 96] + sm->ogB[lane + 96];
            sm->xs[j][lane     ] = y0;  sm->x0s[j][lane     ] = y0;
            sm->xs[j][lane + 32] = y1;  sm->x0s[j][lane + 32] = y1;
            sm->xs[j][lane + 64] = y2;  sm->x0s[j][lane + 64] = y2;
            sm->xs[j][lane + 96] = y3;  sm->x0s[j][lane + 96] = y3;
        }
        __syncthreads();

        for (int it = 0; it < NITER; ++it) {
            // ---- Phase 1: inner LN(xs) -> xnT (transposed), skip gate ----
            for (int j = wid; j < NJ; j += 8) {
                const float v0 = sm->xs[j][lane];
                const float v1 = sm->xs[j][lane + 32];
                const float v2 = sm->xs[j][lane + 64];
                const float v3 = sm->xs[j][lane + 96];
                float s1 = v0+v1+v2+v3;
                float s2 = v0*v0+v1*v1+v2*v2+v3*v3;
                #pragma unroll
                for (int o = 16; o; o >>= 1) {
                    s1 += __shfl_xor_sync(0xffffffffu, s1, o);
                    s2 += __shfl_xor_sync(0xffffffffu, s2, o);
                }
                const float mean = s1 * (1.0f/ND);
                const float var  = s2 * (1.0f/ND) - mean*mean;
                const float rs = rsqrtf(var + LNEPS);
                const float y0 = (v0-mean)*rs*sm->lnG[lane     ] + sm->lnB[lane     ];
                const float y1 = (v1-mean)*rs*sm->lnG[lane + 32] + sm->lnB[lane + 32];
                const float y2 = (v2-mean)*rs*sm->lnG[lane + 64] + sm->lnB[lane + 64];
                const float y3 = (v3-mean)*rs*sm->lnG[lane + 96] + sm->lnB[lane + 96];
                float dot = y0*sm->aW[lane] + y1*sm->aW[lane+32]
                          + y2*sm->aW[lane+64] + y3*sm->aW[lane+96];
                dot = wredsum(dot);
                if (lane == 0)
                    sm->skipv[j] = 1.0f / (1.0f + expf(-(dot + sm->alpha_b0)));
                sm->xnT[lane     ][j] = y0;
                sm->xnT[lane + 32][j] = y1;
                sm->xnT[lane + 64][j] = y2;
                sm->xnT[lane + 96][j] = y3;
            }
            __syncthreads();

            // ---- Phase 2+3 fused: L = xn@w1+b1, R = xn@w2+b2, V = xn@v_w+v_b ----
            {
                const int n  = tid;
                const int nv = tid & 127;
                ull accL[8], accR[8], accV[4];
                float aL16 = 0.f, aR16 = 0.f, aV16 = 0.f;
                #pragma unroll
                for (int q = 0; q < 8; ++q) { accL[q] = 0ull; accR[q] = 0ull; }
                #pragma unroll
                for (int q = 0; q < 4; ++q) accV[q] = 0ull;

                const float* w1p = w1 + n;
                const float* w2p = w2 + n;
                const float* vwp = vw + nv;

                if (tid < 128) {
                    #pragma unroll 4
                    for (int k = 0; k < ND; ++k) {
                        const float wa = w1p[k*(2*ND)];
                        const float wb = w2p[k*(2*ND)];
                        const float wv = vwp[k*ND];
                        const ull waa = pack2(wa, wa);
                        const ull wbb = pack2(wb, wb);
                        const ull wvv = pack2(wv, wv);
                        const ulonglong2* xr = reinterpret_cast<const ulonglong2*>(&sm->xnT[k][0]);
                        const ulonglong2 pA = xr[0];
                        const ulonglong2 pB = xr[1];
                        const ulonglong2 pC = xr[2];
                        const ulonglong2 pD = xr[3];
                        const float x16 = sm->xnT[k][16];
                        ffma2(accL[0], pA.x, waa); ffma2(accR[0], pA.x, wbb);
                        ffma2(accL[1], pA.y, waa); ffma2(accR[1], pA.y, wbb);
                        ffma2(accL[2], pB.x, waa); ffma2(accR[2], pB.x, wbb);
                        ffma2(accL[3], pB.y, waa); ffma2(accR[3], pB.y, wbb);
                        ffma2(accL[4], pC.x, waa); ffma2(accR[4], pC.x, wbb);
                        ffma2(accL[5], pC.y, waa); ffma2(accR[5], pC.y, wbb);
                        ffma2(accL[6], pD.x, waa); ffma2(accR[6], pD.x, wbb);
                        ffma2(accL[7], pD.y, waa); ffma2(accR[7], pD.y, wbb);
                        aL16 = fmaf(x16, wa, aL16);
                        aR16 = fmaf(x16, wb, aR16);
                        ffma2(accV[0], pA.x, wvv); ffma2(accV[1], pA.y, wvv);
                        ffma2(accV[2], pB.x, wvv); ffma2(accV[3], pB.y, wvv);
                        aV16 = fmaf(x16, wv, aV16);
                    }
                } else {
                    #pragma unroll 4
                    for (int k = 0; k < ND; ++k) {
                        const float wa = w1p[k*(2*ND)];
                        const float wb = w2p[k*(2*ND)];
                        const float wv = vwp[k*ND];
                        const ull waa = pack2(wa, wa);
                        const ull wbb = pack2(wb, wb);
                        const ull wvv = pack2(wv, wv);
                        const ulonglong2* xr = reinterpret_cast<const ulonglong2*>(&sm->xnT[k][0]);
                        const ulonglong2 pA = xr[0];
                        const ulonglong2 pB = xr[1];
                        const ulonglong2 pC = xr[2];
                        const ulonglong2 pD = xr[3];
                        const float x16 = sm->xnT[k][16];
                        ffma2(accL[0], pA.x, waa); ffma2(accR[0], pA.x, wbb);
                        ffma2(accL[1], pA.y, waa); ffma2(accR[1], pA.y, wbb);
                        ffma2(accL[2], pB.x, waa); ffma2(accR[2], pB.x, wbb);
                        ffma2(accL[3], pB.y, waa); ffma2(accR[3], pB.y, wbb);
                        ffma2(accL[4], pC.x, waa); ffma2(accR[4], pC.x, wbb);
                        ffma2(accL[5], pC.y, waa); ffma2(accR[5], pC.y, wbb);
                        ffma2(accL[6], pD.x, waa); ffma2(accR[6], pD.x, wbb);
                        ffma2(accL[7], pD.y, waa); ffma2(accR[7], pD.y, wbb);
                        aL16 = fmaf(x16, wa, aL16);
                        aR16 = fmaf(x16, wb, aR16);
                        ffma2(accV[0], pC.x, wvv); ffma2(accV[1], pC.y, wvv);
                        ffma2(accV[2], pD.x, wvv); ffma2(accV[3], pD.y, wvv);
                    }
                }

                const float bb1 = sm->b1s[n], bb2 = sm->b2s[n];
                #pragma unroll
                for (int q = 0; q < 8; ++q) {
                    const float2 l2 = unpack2(accL[q]);
                    const float2 r2 = unpack2(accR[q]);
                    sm->Ls[2*q  ][n] = l2.x + bb1;
                    sm->Ls[2*q+1][n] = l2.y + bb1;
                    sm->Rs[2*q  ][n] = r2.x + bb2;
                    sm->Rs[2*q+1][n] = r2.y + bb2;
                }
                sm->Ls[16][n] = aL16 + bb1;
                sm->Rs[16][n] = aR16 + bb2;

                const float bbv = sm->vbs[nv];
                if (tid < 128) {
                    #pragma unroll
                    for (int q = 0; q < 4; ++q) {
                        const float2 v2 = unpack2(accV[q]);
                        sm->Vs[2*q  ][nv] = v2.x + bbv;
                        sm->Vs[2*q+1][nv] = v2.y + bbv;
                    }
                    sm->Vs[16][nv] = aV16 + bbv;
                } else {
                    #pragma unroll
                    for (int q = 0; q < 4; ++q) {
                        const float2 v2 = unpack2(accV[q]);
                        sm->Vs[8+2*q  ][nv] = v2.x + bbv;
                        sm->Vs[8+2*q+1][nv] = v2.y + bbv;
                    }
                }
            }
            __syncthreads();

            // ---- Phase 4+5 fused: per-(h,i) edge scores + softmax + aggregate
            //      + gelu + skip combine -> xs. No cross-unit score sharing needed.
            for (int u = wid; u < 2*NJ; u += 8) {
                const int h  = (u >= NJ) ? 1 : 0;
                const int i  = u - h*NJ;
                const int o0 = c_nbr_off[i];
                const int deg = c_nbr_off[i+1] - o0;

                const float4 lv = reinterpret_cast<const float4*>(&sm->Ls[i][h*ND])[lane];
                const float4 pw = reinterpret_cast<const float4*>(sm->psW)[lane];

                float sc[5]; int nb[5];
                #pragma unroll
                for (int d = 0; d < 5; ++d) {
                    const bool valid = d < deg;
                    nb[d] = valid ? c_nbr[o0 + d] : i;
                    const float4 rv = reinterpret_cast<const float4*>(&sm->Rs[nb[d]][h*ND])[lane];
                    float z, acc;
                    z = lv.x + rv.x; z = fmaxf(z, 0.2f*z); acc  = z*pw.x;
                    z = lv.y + rv.y; z = fmaxf(z, 0.2f*z); acc += z*pw.y;
                    z = lv.z + rv.z; z = fmaxf(z, 0.2f*z); acc += z*pw.z;
                    z = lv.w + rv.w; z = fmaxf(z, 0.2f*z); acc += z*pw.w;
                    sc[d] = acc;
                }
                // 5 interleaved warp reductions (chains overlap)
                #pragma unroll
                for (int o = 16; o; o >>= 1) {
                    sc[0] += __shfl_xor_sync(0xffffffffu, sc[0], o);
                    sc[1] += __shfl_xor_sync(0xffffffffu, sc[1], o);
                    sc[2] += __shfl_xor_sync(0xffffffffu, sc[2], o);
                    sc[3] += __shfl_xor_sync(0xffffffffu, sc[3], o);
                    sc[4] += __shfl_xor_sync(0xffffffffu, sc[4], o);
                }
                const float psb0 = sm->ps_b0;
                #pragma unroll
                for (int d = 0; d < 5; ++d)
                    sc[d] = (d < deg) ? sc[d] + psb0 : -1e30f;

                float m = sc[0];
                #pragma unroll
                for (int d = 1; d < 5; ++d) m = fmaxf(m, sc[d]);
                float den = 0.f;
                #pragma unroll
                for (int d = 0; d < 5; ++d) { sc[d] = expf(sc[d] - m); den += sc[d]; }
                const float inv = 1.0f / den;

                float acc0 = 0.f, acc1 = 0.f;
                #pragma unroll
                for (int d = 0; d < 5; ++d) {
                    const float* vr = &sm->Vs[nb[d]][h*NDH];
                    acc0 = fmaf(sc[d], vr[lane],      acc0);
                    acc1 = fmaf(sc[d], vr[lane + 32], acc1);
                }
                acc0 *= inv; acc1 *= inv;
                acc0 = 0.5f*acc0*(1.0f + erff(acc0*0.70710678118654752f));
                acc1 = 0.5f*acc1*(1.0f + erff(acc1*0.70710678118654752f));
                const float sk = sm->skipv[i];
                const int c0 = h*NDH + lane;
                sm->xs[i][c0]      = (1.0f - sk)*acc0 + sk*sm->x0s[i][c0];
                sm->xs[i][c0+32]   = (1.0f - sk)*acc1 + sk*sm->x0s[i][c0+32];
            }
            __syncthreads();
        }

        // ---- write result (next-tile-top sync protects xs reuse) ----
        float* og_out = out + (size_t)tile * NJ * ND;
        for (int j = wid; j < NJ; j += 8) {
            reinterpret_cast<float4*>(og_out + j*ND)[lane] =
                reinterpret_cast<const float4*>(sm->xs[j])[lane];
        }
    }
}

extern "C" void kernel_launch(void* const* d_in, const int* in_sizes, int n_in,
                              void* d_out, int out_size) {
    const float* x   = (const float*)d_in[0];
    const float* og  = (const float*)d_in[1];
    const float* ob  = (const float*)d_in[2];
    const float* lg  = (const float*)d_in[3];
    const float* lb  = (const float*)d_in[4];
    const float* aw  = (const float*)d_in[5];
    const float* ab  = (const float*)d_in[6];
    const float* w1  = (const float*)d_in[7];
    const float* b1  = (const float*)d_in[8];
    const float* w2  = (const float*)d_in[9];
    const float* b2  = (const float*)d_in[10];
    const float* psw = (const float*)d_in[11];
    const float* psb = (const float*)d_in[12];
    const float* vw  = (const float*)d_in[13];
    const float* vb  = (const float*)d_in[14];

    const int tiles = in_sizes[0] / (NJ * ND);  // 3888
    const int grid  = (tiles < GRID_PERSIST) ? tiles : GRID_PERSIST;
    const size_t smem_bytes = sizeof(SmemLayout);
    cudaFuncSetAttribute(spatial_appnp_kernel,
                         cudaFuncAttributeMaxDynamicSharedMemorySize,
                         (int)smem_bytes);
    spatial_appnp_kernel<<<grid, NTHREADS, smem_bytes>>>(
        x, og, ob, lg, lb, aw, ab, w1, b1, w2, b2, psw, psb, vw, vb,
        (float*)d_out, tiles);
}

// round 6
// speedup vs baseline: 1.0623x; 1.0623x over previous
#include <cuda_runtime.h>
#include <math.h>

#define NJ 17
#define ND 128
#define NH 2
#define NDH 64
#define NITER 4
#define LNEPS 1e-5f
#define NTHREADS 256
#define XSTR 20          // padded row stride for transposed xn tile (80B: 16B-aligned rows)

typedef unsigned long long ull;

// ---- fixed 17-node skeleton adjacency (incl. self), flattened neighbor lists ----
__constant__ int c_nbr_off[18] = {0,4,7,10,12,15,18,20,23,28,31,33,36,39,41,44,47,49};
__constant__ int c_nbr[49] = {
    0,1,4,7,  0,1,2,  1,2,3,  2,3,  0,4,5,  4,5,6,  5,6,  0,7,8,
    7,8,9,11,14,  8,9,10,  9,10,  8,11,12,  11,12,13,  12,13,
    8,14,15,  14,15,16,  15,16};

// float4/LDS.128 members must be 16B aligned (R1 lesson).
struct SmemLayout {
    alignas(16) float xs[NJ][ND];
    alignas(16) float x0s[NJ][ND];
    alignas(16) float xnT[ND][XSTR];   // row stride 80B (16-mult)
    alignas(16) float Ls[NJ][2*ND];
    alignas(16) float Rs[NJ][2*ND];
    alignas(16) float Vs[NJ][ND];
    alignas(16) float skipv[NJ];
    alignas(16) float lnG[ND];
    alignas(16) float lnB[ND];
    alignas(16) float aW[ND];
    alignas(16) float psW[ND];
    alignas(16) float vbs[ND];
    alignas(16) float b1s[2*ND];
    alignas(16) float b2s[2*ND];
    alignas(16) float alpha_b0;
    float ps_b0;
};

__device__ __forceinline__ float wredsum(float v) {
    #pragma unroll
    for (int o = 16; o; o >>= 1) v += __shfl_xor_sync(0xffffffffu, v, o);
    return v;
}

// ---- packed fp32x2 helpers (sm_103a FFMA2 path) ----
__device__ __forceinline__ void ffma2(ull& d, ull a, ull b) {
    asm("fma.rn.f32x2 %0, %1, %2, %0;" : "+l"(d) : "l"(a), "l"(b));
}
__device__ __forceinline__ ull pack2(float lo, float hi) {
    ull r; asm("mov.b64 %0, {%1, %2};" : "=l"(r) : "f"(lo), "f"(hi)); return r;
}
__device__ __forceinline__ float2 unpack2(ull v) {
    float lo, hi; asm("mov.b64 {%0, %1}, %2;" : "=f"(lo), "=f"(hi) : "l"(v));
    return make_float2(lo, hi);
}

__global__ void __launch_bounds__(NTHREADS, 2)
spatial_appnp_kernel(
    const float* __restrict__ x,
    const float* __restrict__ og,  const float* __restrict__ ob,
    const float* __restrict__ lg,  const float* __restrict__ lb,
    const float* __restrict__ aw,  const float* __restrict__ ab,
    const float* __restrict__ w1,  const float* __restrict__ b1,
    const float* __restrict__ w2,  const float* __restrict__ b2,
    const float* __restrict__ psw, const float* __restrict__ psb,
    const float* __restrict__ vw,  const float* __restrict__ vb,
    float* __restrict__ out)
{
    extern __shared__ float smem_raw[];
    SmemLayout* sm = reinterpret_cast<SmemLayout*>(smem_raw);

    const int tid  = threadIdx.x;
    const int lane = tid & 31;
    const int wid  = tid >> 5;
    const int tile = blockIdx.x;
    const float* xg = x + (size_t)tile * NJ * ND;

    // ---- parameter staging (consumed after the first __syncthreads) ----
    for (int i = tid; i < ND; i += NTHREADS) {
        sm->lnG[i] = lg[i]; sm->lnB[i] = lb[i];
        sm->aW[i]  = aw[i]; sm->psW[i] = psw[i];
        sm->vbs[i] = vb[i];
    }
    for (int i = tid; i < 2*ND; i += NTHREADS) { sm->b1s[i] = b1[i]; sm->b2s[i] = b2[i]; }
    if (tid == 0) { sm->alpha_b0 = ab[0]; sm->ps_b0 = psb[0]; }

    // ---- outer LayerNorm: x -> xs, x0s (interleaved channels, one-pass var) ----
    for (int j = wid; j < NJ; j += 8) {
        const float v0 = xg[j*ND + lane];
        const float v1 = xg[j*ND + lane + 32];
        const float v2 = xg[j*ND + lane + 64];
        const float v3 = xg[j*ND + lane + 96];
        float s1 = v0+v1+v2+v3;
        float s2 = v0*v0+v1*v1+v2*v2+v3*v3;
        #pragma unroll
        for (int o = 16; o; o >>= 1) {
            s1 += __shfl_xor_sync(0xffffffffu, s1, o);
            s2 += __shfl_xor_sync(0xffffffffu, s2, o);
        }
        const float mean = s1 * (1.0f/ND);
        const float var  = s2 * (1.0f/ND) - mean*mean;
        const float rs = rsqrtf(var + LNEPS);
        const float y0 = (v0-mean)*rs*og[lane     ] + ob[lane     ];
        const float y1 = (v1-mean)*rs*og[lane + 32] + ob[lane + 32];
        const float y2 = (v2-mean)*rs*og[lane + 64] + ob[lane + 64];
        const float y3 = (v3-mean)*rs*og[lane + 96] + ob[lane + 96];
        sm->xs[j][lane     ] = y0;  sm->x0s[j][lane     ] = y0;
        sm->xs[j][lane + 32] = y1;  sm->x0s[j][lane + 32] = y1;
        sm->xs[j][lane + 64] = y2;  sm->x0s[j][lane + 64] = y2;
        sm->xs[j][lane + 96] = y3;  sm->x0s[j][lane + 96] = y3;
    }
    __syncthreads();

    for (int it = 0; it < NITER; ++it) {
        // ---- Phase 1: inner LN(xs) -> xnT (transposed), skip gate ----
        for (int j = wid; j < NJ; j += 8) {
            const float v0 = sm->xs[j][lane];
            const float v1 = sm->xs[j][lane + 32];
            const float v2 = sm->xs[j][lane + 64];
            const float v3 = sm->xs[j][lane + 96];
            float s1 = v0+v1+v2+v3;
            float s2 = v0*v0+v1*v1+v2*v2+v3*v3;
            #pragma unroll
            for (int o = 16; o; o >>= 1) {
                s1 += __shfl_xor_sync(0xffffffffu, s1, o);
                s2 += __shfl_xor_sync(0xffffffffu, s2, o);
            }
            const float mean = s1 * (1.0f/ND);
            const float var  = s2 * (1.0f/ND) - mean*mean;
            const float rs = rsqrtf(var + LNEPS);
            const float y0 = (v0-mean)*rs*sm->lnG[lane     ] + sm->lnB[lane     ];
            const float y1 = (v1-mean)*rs*sm->lnG[lane + 32] + sm->lnB[lane + 32];
            const float y2 = (v2-mean)*rs*sm->lnG[lane + 64] + sm->lnB[lane + 64];
            const float y3 = (v3-mean)*rs*sm->lnG[lane + 96] + sm->lnB[lane + 96];
            float dot = y0*sm->aW[lane] + y1*sm->aW[lane+32]
                      + y2*sm->aW[lane+64] + y3*sm->aW[lane+96];
            dot = wredsum(dot);
            if (lane == 0)
                sm->skipv[j] = 1.0f / (1.0f + expf(-(dot + sm->alpha_b0)));
            sm->xnT[lane     ][j] = y0;
            sm->xnT[lane + 32][j] = y1;
            sm->xnT[lane + 64][j] = y2;
            sm->xnT[lane + 96][j] = y3;
        }
        __syncthreads();

        // ---- Phase 2+3 fused: L = xn@w1+b1, R = xn@w2+b2, V = xn@v_w+v_b ----
        {
            const int n  = tid;
            const int nv = tid & 127;
            ull accL[8], accR[8], accV[4];
            float aL16 = 0.f, aR16 = 0.f, aV16 = 0.f;
            #pragma unroll
            for (int q = 0; q < 8; ++q) { accL[q] = 0ull; accR[q] = 0ull; }
            #pragma unroll
            for (int q = 0; q < 4; ++q) accV[q] = 0ull;

            const float* w1p = w1 + n;
            const float* w2p = w2 + n;
            const float* vwp = vw + nv;

            if (tid < 128) {
                #pragma unroll 4
                for (int k = 0; k < ND; ++k) {
                    const float wa = w1p[k*(2*ND)];
                    const float wb = w2p[k*(2*ND)];
                    const float wv = vwp[k*ND];
                    const ull waa = pack2(wa, wa);
                    const ull wbb = pack2(wb, wb);
                    const ull wvv = pack2(wv, wv);
                    const ulonglong2* xr = reinterpret_cast<const ulonglong2*>(&sm->xnT[k][0]);
                    const ulonglong2 pA = xr[0];
                    const ulonglong2 pB = xr[1];
                    const ulonglong2 pC = xr[2];
                    const ulonglong2 pD = xr[3];
                    const float x16 = sm->xnT[k][16];
                    ffma2(accL[0], pA.x, waa); ffma2(accR[0], pA.x, wbb);
                    ffma2(accL[1], pA.y, waa); ffma2(accR[1], pA.y, wbb);
                    ffma2(accL[2], pB.x, waa); ffma2(accR[2], pB.x, wbb);
                    ffma2(accL[3], pB.y, waa); ffma2(accR[3], pB.y, wbb);
                    ffma2(accL[4], pC.x, waa); ffma2(accR[4], pC.x, wbb);
                    ffma2(accL[5], pC.y, waa); ffma2(accR[5], pC.y, wbb);
                    ffma2(accL[6], pD.x, waa); ffma2(accR[6], pD.x, wbb);
                    ffma2(accL[7], pD.y, waa); ffma2(accR[7], pD.y, wbb);
                    aL16 = fmaf(x16, wa, aL16);
                    aR16 = fmaf(x16, wb, aR16);
                    ffma2(accV[0], pA.x, wvv); ffma2(accV[1], pA.y, wvv);
                    ffma2(accV[2], pB.x, wvv); ffma2(accV[3], pB.y, wvv);
                    aV16 = fmaf(x16, wv, aV16);
                }
            } else {
                #pragma unroll 4
                for (int k = 0; k < ND; ++k) {
                    const float wa = w1p[k*(2*ND)];
                    const float wb = w2p[k*(2*ND)];
                    const float wv = vwp[k*ND];
                    const ull waa = pack2(wa, wa);
                    const ull wbb = pack2(wb, wb);
                    const ull wvv = pack2(wv, wv);
                    const ulonglong2* xr = reinterpret_cast<const ulonglong2*>(&sm->xnT[k][0]);
                    const ulonglong2 pA = xr[0];
                    const ulonglong2 pB = xr[1];
                    const ulonglong2 pC = xr[2];
                    const ulonglong2 pD = xr[3];
                    const float x16 = sm->xnT[k][16];
                    ffma2(accL[0], pA.x, waa); ffma2(accR[0], pA.x, wbb);
                    ffma2(accL[1], pA.y, waa); ffma2(accR[1], pA.y, wbb);
                    ffma2(accL[2], pB.x, waa); ffma2(accR[2], pB.x, wbb);
                    ffma2(accL[3], pB.y, waa); ffma2(accR[3], pB.y, wbb);
                    ffma2(accL[4], pC.x, waa); ffma2(accR[4], pC.x, wbb);
                    ffma2(accL[5], pC.y, waa); ffma2(accR[5], pC.y, wbb);
                    ffma2(accL[6], pD.x, waa); ffma2(accR[6], pD.x, wbb);
                    ffma2(accL[7], pD.y, waa); ffma2(accR[7], pD.y, wbb);
                    aL16 = fmaf(x16, wa, aL16);
                    aR16 = fmaf(x16, wb, aR16);
                    ffma2(accV[0], pC.x, wvv); ffma2(accV[1], pC.y, wvv);
                    ffma2(accV[2], pD.x, wvv); ffma2(accV[3], pD.y, wvv);
                }
            }

            const float bb1 = sm->b1s[n], bb2 = sm->b2s[n];
            #pragma unroll
            for (int q = 0; q < 8; ++q) {
                const float2 l2 = unpack2(accL[q]);
                const float2 r2 = unpack2(accR[q]);
                sm->Ls[2*q  ][n] = l2.x + bb1;
                sm->Ls[2*q+1][n] = l2.y + bb1;
                sm->Rs[2*q  ][n] = r2.x + bb2;
                sm->Rs[2*q+1][n] = r2.y + bb2;
            }
            sm->Ls[16][n] = aL16 + bb1;
            sm->Rs[16][n] = aR16 + bb2;

            const float bbv = sm->vbs[nv];
            if (tid < 128) {
                #pragma unroll
                for (int q = 0; q < 4; ++q) {
                    const float2 v2 = unpack2(accV[q]);
                    sm->Vs[2*q  ][nv] = v2.x + bbv;
                    sm->Vs[2*q+1][nv] = v2.y + bbv;
                }
                sm->Vs[16][nv] = aV16 + bbv;
            } else {
                #pragma unroll
                for (int q = 0; q < 4; ++q) {
                    const float2 v2 = unpack2(accV[q]);
                    sm->Vs[8+2*q  ][nv] = v2.x + bbv;
                    sm->Vs[8+2*q+1][nv] = v2.y + bbv;
                }
            }
        }
        __syncthreads();

        // ---- Phase 4+5 fused: per-(h,i) edge scores + softmax + aggregate
        //      + gelu + skip combine -> xs ----
        for (int u = wid; u < 2*NJ; u += 8) {
            const int h  = (u >= NJ) ? 1 : 0;
            const int i  = u - h*NJ;
            const int o0 = c_nbr_off[i];
            const int deg = c_nbr_off[i+1] - o0;

            const float4 lv = reinterpret_cast<const float4*>(&sm->Ls[i][h*ND])[lane];
            const float4 pw = reinterpret_cast<const float4*>(sm->psW)[lane];

            float sc[5]; int nb[5];
            #pragma unroll
            for (int d = 0; d < 5; ++d) {
                const bool valid = d < deg;
                nb[d] = valid ? c_nbr[o0 + d] : i;
                const float4 rv = reinterpret_cast<const float4*>(&sm->Rs[nb[d]][h*ND])[lane];
                float z, acc;
                z = lv.x + rv.x; z = fmaxf(z, 0.2f*z); acc  = z*pw.x;
                z = lv.y + rv.y; z = fmaxf(z, 0.2f*z); acc += z*pw.y;
                z = lv.z + rv.z; z = fmaxf(z, 0.2f*z); acc += z*pw.z;
                z = lv.w + rv.w; z = fmaxf(z, 0.2f*z); acc += z*pw.w;
                sc[d] = acc;
            }
            // 5 interleaved warp reductions (chains overlap)
            #pragma unroll
            for (int o = 16; o; o >>= 1) {
                sc[0] += __shfl_xor_sync(0xffffffffu, sc[0], o);
                sc[1] += __shfl_xor_sync(0xffffffffu, sc[1], o);
                sc[2] += __shfl_xor_sync(0xffffffffu, sc[2], o);
                sc[3] += __shfl_xor_sync(0xffffffffu, sc[3], o);
                sc[4] += __shfl_xor_sync(0xffffffffu, sc[4], o);
            }
            const float psb0 = sm->ps_b0;
            #pragma unroll
            for (int d = 0; d < 5; ++d)
                sc[d] = (d < deg) ? sc[d] + psb0 : -1e30f;

            float m = sc[0];
            #pragma unroll
            for (int d = 1; d < 5; ++d) m = fmaxf(m, sc[d]);
            float den = 0.f;
            #pragma unroll
            for (int d = 0; d < 5; ++d) { sc[d] = expf(sc[d] - m); den += sc[d]; }
            const float inv = 1.0f / den;

            float acc0 = 0.f, acc1 = 0.f;
            #pragma unroll
            for (int d = 0; d < 5; ++d) {
                const float* vr = &sm->Vs[nb[d]][h*NDH];
                acc0 = fmaf(sc[d], vr[lane],      acc0);
                acc1 = fmaf(sc[d], vr[lane + 32], acc1);
            }
            acc0 *= inv; acc1 *= inv;
            acc0 = 0.5f*acc0*(1.0f + erff(acc0*0.70710678118654752f));
            acc1 = 0.5f*acc1*(1.0f + erff(acc1*0.70710678118654752f));
            const float sk = sm->skipv[i];
            const int c0 = h*NDH + lane;
            sm->xs[i][c0]      = (1.0f - sk)*acc0 + sk*sm->x0s[i][c0];
            sm->xs[i][c0+32]   = (1.0f - sk)*acc1 + sk*sm->x0s[i][c0+32];
        }
        __syncthreads();
    }

    // ---- write result ----
    float* og_out = out + (size_t)tile * NJ * ND;
    for (int j = wid; j < NJ; j += 8) {
        reinterpret_cast<float4*>(og_out + j*ND)[lane] =
            reinterpret_cast<const float4*>(sm->xs[j])[lane];
    }
}

extern "C" void kernel_launch(void* const* d_in, const int* in_sizes, int n_in,
                              void* d_out, int out_size) {
    const float* x   = (const float*)d_in[0];
    const float* og  = (const float*)d_in[1];
    const float* ob  = (const float*)d_in[2];
    const float* lg  = (const float*)d_in[3];
    const float* lb  = (const float*)d_in[4];
    const float* aw  = (const float*)d_in[5];
    const float* ab  = (const float*)d_in[6];
    const float* w1  = (const float*)d_in[7];
    const float* b1  = (const float*)d_in[8];
    const float* w2  = (const float*)d_in[9];
    const float* b2  = (const float*)d_in[10];
    const float* psw = (const float*)d_in[11];
    const float* psb = (const float*)d_in[12];
    const float* vw  = (const float*)d_in[13];
    const float* vb  = (const float*)d_in[14];

    const int tiles = in_sizes[0] / (NJ * ND);  // 3888
    const size_t smem_bytes = sizeof(SmemLayout);
    cudaFuncSetAttribute(spatial_appnp_kernel,
                         cudaFuncAttributeMaxDynamicSharedMemorySize,
                         (int)smem_bytes);
    spatial_appnp_kernel<<<tiles, NTHREADS, smem_bytes>>>(
        x, og, ob, lg, lb, aw, ab, w1, b1, w2, b2, psw, psb, vw, vb,
        (float*)d_out);
}